// round 4
// baseline (speedup 1.0000x reference)
#include <cuda_runtime.h>
#include <math.h>

#define D_ 128
#define NB_ 20
#define EMAX 200000
#define FULLMASK 0xffffffffu

typedef unsigned long long u64;

// ---------------- f32x2 packed-math helpers (FFMA2: ptxas won't auto-fuse) ----------------
__device__ __forceinline__ u64 pack2(float lo, float hi) {
    u64 r; asm("mov.b64 %0, {%1, %2};" : "=l"(r) : "f"(lo), "f"(hi)); return r;
}
__device__ __forceinline__ void unpack2(u64 v, float& lo, float& hi) {
    asm("mov.b64 {%0, %1}, %2;" : "=f"(lo), "=f"(hi) : "l"(v));
}
__device__ __forceinline__ void ffma2(u64& d, u64 a, u64 b) {
    asm("fma.rn.f32x2 %0, %1, %2, %0;" : "+l"(d) : "l"(a), "l"(b));
}
__device__ __forceinline__ u64 fadd2(u64 a, u64 b) {
    u64 r; asm("add.rn.f32x2 %0, %1, %2;" : "=l"(r) : "l"(a), "l"(b)); return r;
}

// ---------------- scratch (device globals; no allocation allowed) ----------------
__device__ float g_P[(size_t)EMAX * D_];    // edge_attr @ W1[0:128]
__device__ float g_Q[(size_t)EMAX * D_];    // edge_attr @ W1[128:256]
__device__ int   g_cnt[EMAX];               // triplet count per e_ij (for b2 term)
__device__ float g_Wc[D_ * D_];             // W2 @ Wu
__device__ float g_bcu[D_];                 // b2 @ Wu
__device__ float g_A2c[NB_ * D_];           // A2 @ W1c   (W1c = W1 rows 256..275)
__device__ float g_b1p[D_];                 // b1 + ab2 @ W1c

// ---------------- zero scratch (S lives in d_out) ----------------
__global__ void zero_kernel(float* __restrict__ S, int E) {
    const int stride = gridDim.x * blockDim.x;
    const int n4 = E * (D_ / 4);
    float4 z = make_float4(0.f, 0.f, 0.f, 0.f);
    for (int i = blockIdx.x * blockDim.x + threadIdx.x; i < n4; i += stride)
        reinterpret_cast<float4*>(S)[i] = z;
    for (int i = blockIdx.x * blockDim.x + threadIdx.x; i < E; i += stride)
        g_cnt[i] = 0;
}

// ---------------- tiny precompute: Wc, bcu, A2c, b1p ----------------
__global__ void prep_kernel(const float* __restrict__ W2, const float* __restrict__ Wu,
                            const float* __restrict__ b2, const float* __restrict__ A2,
                            const float* __restrict__ W1, const float* __restrict__ ab2,
                            const float* __restrict__ b1) {
    const int c = threadIdx.x;           // 0..127
    const int blk = blockIdx.x;
    if (blk < 128) {
        float acc = 0.f;
        #pragma unroll 4
        for (int j = 0; j < 128; j++) acc = fmaf(W2[blk * 128 + j], Wu[j * 128 + c], acc);
        g_Wc[blk * 128 + c] = acc;
    } else if (blk < 128 + NB_) {
        const int k = blk - 128;
        float acc = 0.f;
        #pragma unroll
        for (int j = 0; j < NB_; j++) acc = fmaf(A2[k * NB_ + j], W1[(256 + j) * 128 + c], acc);
        g_A2c[k * 128 + c] = acc;
    } else {
        float acc = 0.f;
        #pragma unroll 4
        for (int j = 0; j < 128; j++) acc = fmaf(b2[j], Wu[j * 128 + c], acc);
        g_bcu[c] = acc;
        float acc2 = b1[c];
        #pragma unroll
        for (int j = 0; j < NB_; j++) acc2 = fmaf(ab2[j], W1[(256 + j) * 128 + c], acc2);
        g_b1p[c] = acc2;
    }
}

// ---------------- fp32 tiled GEMM: C[M x 128] = A[M x 128] @ B[128 x 128] (+epilogue) ----------------
// 128x128 block tile, 256 threads, 8x8 per-thread micro-tile via FFMA2, double-buffered smem.
// In-place safe for C == A: block b reads only A rows [b*128, b*128+128), all consumed
// into smem/regs in the mainloop before the epilogue writes those same rows.
__global__ __launch_bounds__(256, 2)
void sgemm128(const float* A, const float* __restrict__ B,
              float* C, int M,
              const float* __restrict__ bias,   // nullable, per-column
              const int* __restrict__ cnt,      // nullable, per-row
              const float* __restrict__ cbias)  // per-column, used with cnt
{
    __shared__ __align__(16) float As[2][8][128];   // [k][m] (transposed A tile)
    __shared__ __align__(16) float Bs[2][8][128];   // [k][n]

    const int tid = threadIdx.x;
    const int row0 = blockIdx.x * 128;
    const int tx = tid & 15;          // col group 0..15
    const int ty = tid >> 4;          // row group 0..15

    const int a_row = tid >> 1;       // 0..127
    const int a_k   = (tid & 1) << 2; // 0 or 4
    const int b_row = tid >> 5;       // 0..7
    const int b_col = (tid & 31) << 2;

    const bool a_valid = (row0 + a_row) < M;
    const float* Ap = A + (size_t)(row0 + a_row) * 128 + a_k;
    const float* Bp = B + b_row * 128 + b_col;

    float4 a4 = a_valid ? *reinterpret_cast<const float4*>(Ap)
                        : make_float4(0.f, 0.f, 0.f, 0.f);
    float4 b4 = *reinterpret_cast<const float4*>(Bp);
    As[0][a_k + 0][a_row] = a4.x;
    As[0][a_k + 1][a_row] = a4.y;
    As[0][a_k + 2][a_row] = a4.z;
    As[0][a_k + 3][a_row] = a4.w;
    *reinterpret_cast<float4*>(&Bs[0][b_row][b_col]) = b4;
    __syncthreads();

    u64 accp[8][4];
    const u64 z2 = pack2(0.f, 0.f);
    #pragma unroll
    for (int i = 0; i < 8; i++)
        #pragma unroll
        for (int j = 0; j < 4; j++) accp[i][j] = z2;

    int buf = 0;
    #pragma unroll 1
    for (int kk = 8; kk <= 128; kk += 8) {
        const bool has_next = (kk < 128);
        float4 na4, nb4;
        if (has_next) {
            na4 = a_valid ? *reinterpret_cast<const float4*>(Ap + kk)
                          : make_float4(0.f, 0.f, 0.f, 0.f);
            nb4 = *reinterpret_cast<const float4*>(Bp + kk * 128);
        }
        #pragma unroll
        for (int k = 0; k < 8; k++) {
            float ar[8];
            *reinterpret_cast<float4*>(&ar[0]) = *reinterpret_cast<const float4*>(&As[buf][k][ty * 8]);
            *reinterpret_cast<float4*>(&ar[4]) = *reinterpret_cast<const float4*>(&As[buf][k][ty * 8 + 4]);
            const ulonglong2 b01 = *reinterpret_cast<const ulonglong2*>(&Bs[buf][k][tx * 8]);
            const ulonglong2 b23 = *reinterpret_cast<const ulonglong2*>(&Bs[buf][k][tx * 8 + 4]);
            u64 brp[4];
            brp[0] = b01.x; brp[1] = b01.y; brp[2] = b23.x; brp[3] = b23.y;
            #pragma unroll
            for (int i = 0; i < 8; i++) {
                const u64 aa = pack2(ar[i], ar[i]);
                ffma2(accp[i][0], aa, brp[0]);
                ffma2(accp[i][1], aa, brp[1]);
                ffma2(accp[i][2], aa, brp[2]);
                ffma2(accp[i][3], aa, brp[3]);
            }
        }
        if (has_next) {
            const int nb = buf ^ 1;
            As[nb][a_k + 0][a_row] = na4.x;
            As[nb][a_k + 1][a_row] = na4.y;
            As[nb][a_k + 2][a_row] = na4.z;
            As[nb][a_k + 3][a_row] = na4.w;
            *reinterpret_cast<float4*>(&Bs[nb][b_row][b_col]) = nb4;
            __syncthreads();
            buf = nb;
        }
    }

    // epilogue
    float4 bias_lo = make_float4(0.f, 0.f, 0.f, 0.f), bias_hi = bias_lo;
    float4 cb_lo = bias_lo, cb_hi = bias_lo;
    if (bias) {
        bias_lo = *reinterpret_cast<const float4*>(bias + tx * 8);
        bias_hi = *reinterpret_cast<const float4*>(bias + tx * 8 + 4);
    }
    if (cnt) {
        cb_lo = *reinterpret_cast<const float4*>(cbias + tx * 8);
        cb_hi = *reinterpret_cast<const float4*>(cbias + tx * 8 + 4);
    }
    #pragma unroll
    for (int i = 0; i < 8; i++) {
        const int r = row0 + ty * 8 + i;
        if (r >= M) continue;
        const float cm = cnt ? (float)cnt[r] : 0.f;
        float c0, c1, c2, c3, c4, c5, c6, c7;
        unpack2(accp[i][0], c0, c1);
        unpack2(accp[i][1], c2, c3);
        unpack2(accp[i][2], c4, c5);
        unpack2(accp[i][3], c6, c7);
        float4 o1, o2;
        o1.x = c0 + bias_lo.x + cm * cb_lo.x;
        o1.y = c1 + bias_lo.y + cm * cb_lo.y;
        o1.z = c2 + bias_lo.z + cm * cb_lo.z;
        o1.w = c3 + bias_lo.w + cm * cb_lo.w;
        o2.x = c4 + bias_hi.x + cm * cb_hi.x;
        o2.y = c5 + bias_hi.y + cm * cb_hi.y;
        o2.z = c6 + bias_hi.z + cm * cb_hi.z;
        o2.w = c7 + bias_hi.w + cm * cb_hi.w;
        float* Cp = C + (size_t)r * 128 + tx * 8;
        *reinterpret_cast<float4*>(Cp) = o1;
        *reinterpret_cast<float4*>(Cp + 4) = o2;
    }
}

// ---------------- per-triplet kernel: one warp per triplet, A2c register-resident ----------------
__device__ __forceinline__ float silu_f(float x) {
    return x / (1.f + __expf(-x));
}

__global__ __launch_bounds__(128, 4)
void triplet_kernel(const int* __restrict__ tbe, const float* __restrict__ ev,
                    const float* __restrict__ A1, const float* __restrict__ ab1,
                    float* __restrict__ S, int T) {
    const int lane = threadIdx.x & 31;
    const int wid  = threadIdx.x >> 5;
    const int wpb  = blockDim.x >> 5;

    // A2c held in registers for the whole kernel: lane owns cols [lane*4, lane*4+4)
    u64 wk0[NB_], wk1[NB_];
    #pragma unroll
    for (int k = 0; k < NB_; k++) {
        const float4 w = *reinterpret_cast<const float4*>(&g_A2c[k * D_ + lane * 4]);
        wk0[k] = pack2(w.x, w.y);
        wk1[k] = pack2(w.z, w.w);
    }
    const float4 b = *reinterpret_cast<const float4*>(&g_b1p[lane * 4]);
    const u64 bp0 = pack2(b.x, b.y);
    const u64 bp1 = pack2(b.z, b.w);

    // per-lane angle-MLP constants (lanes 0..19 active)
    float a10 = 0.f, a11 = 0.f, a12 = 0.f, rab1 = 0.f;
    if (lane < NB_) {
        a10 = A1[0 * NB_ + lane];
        a11 = A1[1 * NB_ + lane];
        a12 = A1[2 * NB_ + lane];
        rab1 = ab1[lane];
    }

    for (int t = blockIdx.x * wpb + wid; t < T; t += gridDim.x * wpb) {
        const int2 e2 = reinterpret_cast<const int2*>(tbe)[t];
        const int e_ij = e2.x;
        const int e_ik = e2.y;

        // geometry (uniform across warp; negation of vectors cancels in len & cos)
        const float vx = ev[e_ij * 3 + 0], vy = ev[e_ij * 3 + 1], vz = ev[e_ij * 3 + 2];
        const float wx = ev[e_ik * 3 + 0], wy = ev[e_ik * 3 + 1], wz = ev[e_ik * 3 + 2];
        const float len_ij = fmaxf(sqrtf(vx * vx + vy * vy + vz * vz), 1e-6f);
        const float len_ik = fmaxf(sqrtf(wx * wx + wy * wy + wz * wz), 1e-6f);
        float cosv = (vx * wx + vy * wy + vz * wz) / (len_ij * len_ik);
        cosv = fminf(fmaxf(cosv, -1.f), 1.f);

        // h1[j] = silu(f @ A1 + ab1), lane j holds h1[j] (j<20)
        const float z = fmaf(len_ij, a10, fmaf(len_ik, a11, fmaf(cosv, a12, rab1)));
        const float h1 = silu_f(z);

        // gather P[e_ij], Q[e_ik] rows (512B coalesced each), pre-packed as f32x2
        const ulonglong2 pv = reinterpret_cast<const ulonglong2*>(g_P + (size_t)e_ij * D_)[lane];
        const ulonglong2 qv = reinterpret_cast<const ulonglong2*>(g_Q + (size_t)e_ik * D_)[lane];

        u64 acc0 = fadd2(fadd2(pv.x, qv.x), bp0);
        u64 acc1 = fadd2(fadd2(pv.y, qv.y), bp1);

        #pragma unroll
        for (int k = 0; k < NB_; k++) {
            const float hk = __shfl_sync(FULLMASK, h1, k);
            const u64 hh = pack2(hk, hk);
            ffma2(acc0, hh, wk0[k]);
            ffma2(acc1, hh, wk1[k]);
        }

        float m0, m1, m2, m3;
        unpack2(acc0, m0, m1);
        unpack2(acc1, m2, m3);
        m0 = silu_f(m0);
        m1 = silu_f(m1);
        m2 = silu_f(m2);
        m3 = silu_f(m3);

        float* dst = S + (size_t)e_ij * D_ + lane * 4;
        asm volatile("red.global.add.v4.f32 [%0], {%1, %2, %3, %4};"
                     :: "l"(dst), "f"(m0), "f"(m1), "f"(m2), "f"(m3) : "memory");
        if (lane == 0) atomicAdd(&g_cnt[e_ij], 1);
    }
}

// ---------------- launch ----------------
extern "C" void kernel_launch(void* const* d_in, const int* in_sizes, int n_in,
                              void* d_out, int out_size) {
    const float* edge_attr = (const float*)d_in[0];
    // d_in[1] = three_body_indices (unused by the math)
    const int*   tbe       = (const int*)d_in[2];
    const float* ev        = (const float*)d_in[3];
    const float* A1        = (const float*)d_in[4];
    const float* ab1       = (const float*)d_in[5];
    const float* W1        = (const float*)d_in[8];
    const float* b1        = (const float*)d_in[9];
    const float* W2        = (const float*)d_in[10];
    const float* b2        = (const float*)d_in[11];
    const float* Wu        = (const float*)d_in[12];
    const float* bu        = (const float*)d_in[13];
    const float* A2        = (const float*)d_in[6];
    const float* ab2       = (const float*)d_in[7];
    float* out = (float*)d_out;

    const int E = in_sizes[0] / D_;
    const int T = in_sizes[2] / 2;

    void *pP, *pQ, *pcnt, *pWc, *pbcu;
    cudaGetSymbolAddress(&pP, g_P);
    cudaGetSymbolAddress(&pQ, g_Q);
    cudaGetSymbolAddress(&pcnt, g_cnt);
    cudaGetSymbolAddress(&pWc, g_Wc);
    cudaGetSymbolAddress(&pbcu, g_bcu);

    // S (segment sum of silu(pre)) lives in d_out; final GEMM is in-place.
    zero_kernel<<<1184, 256>>>(out, E);
    prep_kernel<<<128 + NB_ + 1, 128>>>(W2, Wu, b2, A2, W1, ab2, b1);

    const int gb = (E + 127) / 128;
    sgemm128<<<gb, 256>>>(edge_attr, W1, (float*)pP, E, nullptr, nullptr, nullptr);
    sgemm128<<<gb, 256>>>(edge_attr, W1 + 128 * 128, (float*)pQ, E, nullptr, nullptr, nullptr);

    triplet_kernel<<<2368, 128>>>(tbe, ev, A1, ab1, out, T);

    sgemm128<<<gb, 256>>>(out, (const float*)pWc, out, E,
                          bu, (const int*)pcnt, (const float*)pbcu);
}